// round 5
// baseline (speedup 1.0000x reference)
#include <cuda_runtime.h>
#include <cuda_fp16.h>

#define N_NODES_MAX 50000
#define D 64
#define MAX_DEG 160

// __device__ scratch (no runtime allocation allowed)
__device__ __half2        g_h16[N_NODES_MAX * (D / 2)];    // fp16 copy of h
__device__ int            g_deg[N_NODES_MAX];              // out-degree (src)
__device__ int            g_cnt[N_NODES_MAX];              // in-degree counter
__device__ unsigned short g_bucket[N_NODES_MAX * MAX_DEG]; // src lists per dst

// ---------------------------------------------------------------------------
// Kernel 1: zero counters + convert h -> fp16
// ---------------------------------------------------------------------------
__global__ void __launch_bounds__(256) prep_kernel(const float2* __restrict__ h2,
                                                   int n_nodes) {
    int i = blockIdx.x * blockDim.x + threadIdx.x;
    int stride = gridDim.x * blockDim.x;
    int nelem = n_nodes * (D / 2);
    for (int k = i; k < nelem; k += stride) {
        float2 v = h2[k];
        g_h16[k] = __floats2half2_rn(v.x, v.y);
    }
    for (int k = i; k < n_nodes; k += stride) { g_deg[k] = 0; g_cnt[k] = 0; }
}

// ---------------------------------------------------------------------------
// Kernel 2: build dst->src buckets + out-degree histogram.
// 4 edges per thread via int4 loads: MLP=4 on the atomics, 1/4 the index
// wavefronts. Overflow handled exactly by rescan in the fused kernel.
// ---------------------------------------------------------------------------
__global__ void __launch_bounds__(256) build_kernel(const int4* __restrict__ src4,
                                                    const int4* __restrict__ dst4,
                                                    const int* __restrict__ src,
                                                    const int* __restrict__ dst,
                                                    int n_quads, int n_edges) {
    int q = blockIdx.x * blockDim.x + threadIdx.x;
    if (q < n_quads) {
        int4 s = src4[q];
        int4 d = dst4[q];
        atomicAdd(&g_deg[s.x], 1);
        atomicAdd(&g_deg[s.y], 1);
        atomicAdd(&g_deg[s.z], 1);
        atomicAdd(&g_deg[s.w], 1);
        int p0 = atomicAdd(&g_cnt[d.x], 1);
        int p1 = atomicAdd(&g_cnt[d.y], 1);
        int p2 = atomicAdd(&g_cnt[d.z], 1);
        int p3 = atomicAdd(&g_cnt[d.w], 1);
        if (p0 < MAX_DEG) g_bucket[d.x * MAX_DEG + p0] = (unsigned short)s.x;
        if (p1 < MAX_DEG) g_bucket[d.y * MAX_DEG + p1] = (unsigned short)s.y;
        if (p2 < MAX_DEG) g_bucket[d.z * MAX_DEG + p2] = (unsigned short)s.z;
        if (p3 < MAX_DEG) g_bucket[d.w * MAX_DEG + p3] = (unsigned short)s.w;
    }
    // remainder edges (n_edges % 4) handled by the first few threads
    int r = n_quads * 4 + q;
    if (q < (n_edges - n_quads * 4)) {
        int s = src[r], d = dst[r];
        atomicAdd(&g_deg[s], 1);
        int p = atomicAdd(&g_cnt[d], 1);
        if (p < MAX_DEG) g_bucket[d * MAX_DEG + p] = (unsigned short)s;
    }
}

// ---------------------------------------------------------------------------
// Kernel 3 (fused): gather-aggregate (fp16 rows, fp32 acc, MLP=8)
//                   + GEMM + norm + bias + relu. One warp per node.
// ---------------------------------------------------------------------------
__global__ void __launch_bounds__(256) fused_kernel(const float* __restrict__ hfp32,
                                                    const float* __restrict__ W,
                                                    const float* __restrict__ bias,
                                                    const int* __restrict__ src,
                                                    const int* __restrict__ dst,
                                                    float* __restrict__ out,
                                                    int n_nodes, int n_edges) {
    __shared__ float  Ws[D * D];
    __shared__ float  bs[D];
    __shared__ float2 abuf[8][D / 2];

    int tid = threadIdx.x;
    for (int k = tid; k < D * D; k += blockDim.x) Ws[k] = W[k];
    if (tid < D) bs[tid] = bias[tid];
    __syncthreads();

    int warp = tid >> 5;
    int lane = tid & 31;
    int gw = blockIdx.x * 8 + warp;
    int nwarps = gridDim.x * 8;

    for (int node = gw; node < n_nodes; node += nwarps) {
        int cnt = g_cnt[node];
        float2 acc = make_float2(0.f, 0.f);

        if (cnt <= MAX_DEG) {
            const unsigned short* lst = &g_bucket[node * MAX_DEG];
            int i = 0;
            for (; i + 8 <= cnt; i += 8) {
                ushort4 ia = *reinterpret_cast<const ushort4*>(lst + i);
                ushort4 ib = *reinterpret_cast<const ushort4*>(lst + i + 4);
                float2 v0 = __half22float2(g_h16[(int)ia.x * (D / 2) + lane]);
                float2 v1 = __half22float2(g_h16[(int)ia.y * (D / 2) + lane]);
                float2 v2 = __half22float2(g_h16[(int)ia.z * (D / 2) + lane]);
                float2 v3 = __half22float2(g_h16[(int)ia.w * (D / 2) + lane]);
                float2 v4 = __half22float2(g_h16[(int)ib.x * (D / 2) + lane]);
                float2 v5 = __half22float2(g_h16[(int)ib.y * (D / 2) + lane]);
                float2 v6 = __half22float2(g_h16[(int)ib.z * (D / 2) + lane]);
                float2 v7 = __half22float2(g_h16[(int)ib.w * (D / 2) + lane]);
                acc.x += ((v0.x + v1.x) + (v2.x + v3.x)) + ((v4.x + v5.x) + (v6.x + v7.x));
                acc.y += ((v0.y + v1.y) + (v2.y + v3.y)) + ((v4.y + v5.y) + (v6.y + v7.y));
            }
            for (; i < cnt; i++) {
                float2 v = __half22float2(g_h16[(int)lst[i] * (D / 2) + lane]);
                acc.x += v.x;
                acc.y += v.y;
            }
        } else {
            // exact fallback (statistically never executes): scan all edges
            for (int e = 0; e < n_edges; e++) {
                if (dst[e] == node) {
                    int s = src[e];
                    float2 v = reinterpret_cast<const float2*>(hfp32)[s * (D / 2) + lane];
                    acc.x += v.x;
                    acc.y += v.y;
                }
            }
        }

        // broadcast row via smem, then 64x64 row GEMM
        abuf[warp][lane] = acc;
        __syncwarp();

        float acc0 = 0.f, acc1 = 0.f;
        const float* arow = reinterpret_cast<const float*>(abuf[warp]);
        #pragma unroll
        for (int k = 0; k < D; k++) {
            float av = arow[k];
            acc0 = fmaf(av, Ws[k * D + lane],      acc0);
            acc1 = fmaf(av, Ws[k * D + lane + 32], acc1);
        }

        float norm = rsqrtf((float)g_deg[node]);   // >= 1 via self loops
        float o0 = fmaf(acc0, norm, bs[lane]);
        float o1 = fmaf(acc1, norm, bs[lane + 32]);
        out[node * D + lane]      = fmaxf(o0, 0.f);
        out[node * D + lane + 32] = fmaxf(o1, 0.f);
        __syncwarp();
    }
}

// ---------------------------------------------------------------------------
extern "C" void kernel_launch(void* const* d_in, const int* in_sizes, int n_in,
                              void* d_out, int out_size) {
    const float* h    = (const float*)d_in[0];   // [N, 64]
    const float* W    = (const float*)d_in[1];   // [64, 64]
    const float* bias = (const float*)d_in[2];   // [64]
    const int*   src  = (const int*)d_in[3];     // [E]
    const int*   dst  = (const int*)d_in[4];     // [E]
    float*       out  = (float*)d_out;           // [N, 64]

    int n_nodes = in_sizes[0] / D;
    if (n_nodes > N_NODES_MAX) n_nodes = N_NODES_MAX;
    int n_edges = in_sizes[3];
    int n_quads = n_edges / 4;

    prep_kernel<<<2048, 256>>>(reinterpret_cast<const float2*>(h), n_nodes);

    int bblocks = (n_quads + 255) / 256;
    build_kernel<<<bblocks, 256>>>(reinterpret_cast<const int4*>(src),
                                   reinterpret_cast<const int4*>(dst),
                                   src, dst, n_quads, n_edges);

    int fblocks = (n_nodes + 7) / 8;
    fused_kernel<<<fblocks, 256>>>(h, W, bias, src, dst, out, n_nodes, n_edges);
}